// round 5
// baseline (speedup 1.0000x reference)
#include <cuda_runtime.h>

// CRF loss, T=512, B=1024, K=48.
// One 32-thread warp per block; each warp runs TWO independent batch elements
// (bA = blockIdx.x, bB = blockIdx.x + 512) so the second recursion's issue
// fills the first's latency bubbles. Lanes 0..23 own state pair (2l, 2l+1).
// Linear-space recursion, exact power-of-2 renorm (int exponent accumulator).
// Natural float2 packing: smem P stored as {P_2i, P_2i+1}; one LDS.128 feeds
// 4 states; fma.rn.f32x2 accumulates elementwise, horizontal add at the end.

#define TT 512
#define BB 1024
#define NBLK 512
#define KK 48
#define START_TAG 46
#define STOP_TAG  47
#define LN2F 0.6931471805599453f

__device__ float g_partial[BB];
__device__ int   g_count = 0;   // last block resets to 0 (graph-replay safe)

__device__ __forceinline__ unsigned long long pack2(float lo, float hi) {
    unsigned long long r;
    asm("mov.b64 %0, {%1, %2};" : "=l"(r) : "f"(lo), "f"(hi));
    return r;
}
__device__ __forceinline__ void unpack2(unsigned long long v, float& lo, float& hi) {
    asm("mov.b64 {%0, %1}, %2;" : "=f"(lo), "=f"(hi) : "l"(v));
}
__device__ __forceinline__ unsigned long long fma2(unsigned long long a,
                                                   unsigned long long b,
                                                   unsigned long long c) {
    unsigned long long d;
    asm("fma.rn.f32x2 %0, %1, %2, %3;" : "=l"(d) : "l"(a), "l"(b), "l"(c));
    return d;
}
__device__ __forceinline__ unsigned long long add2(unsigned long long a,
                                                   unsigned long long b) {
    unsigned long long d;
    asm("add.rn.f32x2 %0, %1, %2;" : "=l"(d) : "l"(a), "l"(b));
    return d;
}

__global__ void __launch_bounds__(32, 1) crf_kernel(
    const float* __restrict__ feats,
    const float* __restrict__ trans,
    const int*   __restrict__ tags,
    const int*   __restrict__ lengths,
    float*       __restrict__ out)
{
    __shared__ __align__(16) float2 s_p[2][2][24];  // [batch][ping][pair]
    __shared__ float s_trans[KK * KK];

    const int bA   = blockIdx.x;
    const int bB   = blockIdx.x + NBLK;
    const int lane = threadIdx.x;
    const bool act = (lane < 24);
    const int s0 = 2 * lane;
    const int s1 = 2 * lane + 1;
    const int lenA = __ldg(lengths + bA);
    const int lenB = __ldg(lengths + bB);
    const int lmax = max(lenA, lenB);

    for (int i = lane; i < KK * KK; i += 32) s_trans[i] = trans[i];
    for (int i = lane; i < 24; i += 32) {
        float2 z = make_float2(0.0f, 0.0f);
        float2 v0 = (i == 23) ? make_float2(1.0f, 0.0f) : z;  // START=46 = pair23.x
        s_p[0][0][i] = v0; s_p[0][1][i] = z;
        s_p[1][0][i] = v0; s_p[1][1][i] = z;
    }
    __syncwarp();

    // etp[o][i] = {exp(trans[s, 2i]), exp(trans[s, 2i+1])}, s = 2*lane+o
    unsigned long long etp0[24], etp1[24];
    if (act) {
        #pragma unroll
        for (int i = 0; i < 24; i++) {
            etp0[i] = pack2(__expf(s_trans[s0 * KK + 2*i]),
                            __expf(s_trans[s0 * KK + 2*i + 1]));
            etp1[i] = pack2(__expf(s_trans[s1 * KK + 2*i]),
                            __expf(s_trans[s1 * KK + 2*i + 1]));
        }
    }

    const float* fA = feats + bA * KK;
    const float* fB = feats + bB * KK;
    const size_t FS = (size_t)BB * KK;

    // prefetch pipelines, depth 3 each
    float2 a1 = {0,0}, a2 = {0,0}, a3 = {0,0};
    float2 b1 = {0,0}, b2 = {0,0}, b3 = {0,0};
    if (act) {
        a1 = __ldg((const float2*)(fA + s0));
        if (1 < lenA) a2 = __ldg((const float2*)(fA + 1 * FS + s0));
        if (2 < lenA) a3 = __ldg((const float2*)(fA + 2 * FS + s0));
        b1 = __ldg((const float2*)(fB + s0));
        if (1 < lenB) b2 = __ldg((const float2*)(fB + 1 * FS + s0));
        if (2 < lenB) b3 = __ldg((const float2*)(fB + 2 * FS + s0));
    }
    int CintA = 0, CintB = 0;
    __syncwarp();

    int buf = 0;
    #pragma unroll 1
    for (int t = 0; t < lmax; t++) {
        float2 fcA = a1, fcB = b1;
        a1 = a2; a2 = a3;
        b1 = b2; b2 = b3;
        if (act) {
            a3 = (t + 3 < lenA) ? __ldg((const float2*)(fA + (size_t)(t + 3) * FS + s0))
                                : make_float2(0.0f, 0.0f);
            b3 = (t + 3 < lenB) ? __ldg((const float2*)(fB + (size_t)(t + 3) * FS + s0))
                                : make_float2(0.0f, 0.0f);
        }

        if (act && t < lenA) {
            const ulonglong2* pv = (const ulonglong2*)(s_p[0][buf]);
            ulonglong2 e0 = pv[0];
            float p0 = __uint_as_float((unsigned)e0.x);     // P[0]
            unsigned long long c00 = fma2(e0.x, etp0[0], 0ull);
            unsigned long long c01 = fma2(e0.y, etp0[1], 0ull);
            unsigned long long c10 = fma2(e0.x, etp1[0], 0ull);
            unsigned long long c11 = fma2(e0.y, etp1[1], 0ull);
            #pragma unroll
            for (int q = 1; q < 12; q++) {
                ulonglong2 e = pv[q];                       // states 4q..4q+3
                c00 = fma2(e.x, etp0[2*q],     c00);
                c01 = fma2(e.y, etp0[2*q + 1], c01);
                c10 = fma2(e.x, etp1[2*q],     c10);
                c11 = fma2(e.y, etp1[2*q + 1], c11);
            }
            unsigned int pexp = __float_as_uint(p0) >> 23;
            int pe = (pexp - 1u < 254u) ? (int)pexp - 127 : 0;
            CintA += pe;
            float k = __uint_as_float((unsigned)(127 - pe) << 23);
            float mA0 = __expf(fcA.x) * k, mA1 = __expf(fcA.y) * k;
            float l0, h0, l1, h1;
            unpack2(add2(c00, c01), l0, h0);
            unpack2(add2(c10, c11), l1, h1);
            s_p[0][buf ^ 1][lane] = make_float2((l0 + h0) * mA0, (l1 + h1) * mA1);
        }
        if (act && t < lenB) {
            const ulonglong2* pv = (const ulonglong2*)(s_p[1][buf]);
            ulonglong2 e0 = pv[0];
            float p0 = __uint_as_float((unsigned)e0.x);
            unsigned long long c00 = fma2(e0.x, etp0[0], 0ull);
            unsigned long long c01 = fma2(e0.y, etp0[1], 0ull);
            unsigned long long c10 = fma2(e0.x, etp1[0], 0ull);
            unsigned long long c11 = fma2(e0.y, etp1[1], 0ull);
            #pragma unroll
            for (int q = 1; q < 12; q++) {
                ulonglong2 e = pv[q];
                c00 = fma2(e.x, etp0[2*q],     c00);
                c01 = fma2(e.y, etp0[2*q + 1], c01);
                c10 = fma2(e.x, etp1[2*q],     c10);
                c11 = fma2(e.y, etp1[2*q + 1], c11);
            }
            unsigned int pexp = __float_as_uint(p0) >> 23;
            int pe = (pexp - 1u < 254u) ? (int)pexp - 127 : 0;
            CintB += pe;
            float k = __uint_as_float((unsigned)(127 - pe) << 23);
            float mB0 = __expf(fcB.x) * k, mB1 = __expf(fcB.y) * k;
            float l0, h0, l1, h1;
            unpack2(add2(c00, c01), l0, h0);
            unpack2(add2(c10, c11), l1, h1);
            s_p[1][buf ^ 1][lane] = make_float2((l0 + h0) * mB0, (l1 + h1) * mB1);
        }
        __syncwarp();
        buf ^= 1;
    }

    // finals: batch X's last P lives in buffer (lenX & 1)
    float vA = 0.0f, vB = 0.0f;
    if (act) {
        float eS0 = __expf(s_trans[STOP_TAG * KK + s0]);
        float eS1 = __expf(s_trans[STOP_TAG * KK + s1]);
        float2 PA = s_p[0][lenA & 1][lane];
        float2 PB = s_p[1][lenB & 1][lane];
        vA = PA.x * eS0 + PA.y * eS1;
        vB = PB.x * eS0 + PB.y * eS1;
    }
    #pragma unroll
    for (int o = 16; o; o >>= 1) {
        vA += __shfl_xor_sync(~0u, vA, o);
        vB += __shfl_xor_sync(~0u, vB, o);
    }
    float logzA = (float)CintA * LN2F + __logf(vA);
    float logzB = (float)CintB * LN2F + __logf(vB);

    // gold scores (all 32 lanes)
    const int* tgA = tags + bA * TT;
    const int* tgB = tags + bB * TT;
    float gA = 0.0f, gB = 0.0f;
    for (int t = lane; t < lenA; t += 32) {
        int nxt = __ldg(tgA + t);
        int prv = (t == 0) ? START_TAG : __ldg(tgA + t - 1);
        gA += s_trans[nxt * KK + prv] + __ldg(fA + (size_t)t * FS + nxt);
    }
    for (int t = lane; t < lenB; t += 32) {
        int nxt = __ldg(tgB + t);
        int prv = (t == 0) ? START_TAG : __ldg(tgB + t - 1);
        gB += s_trans[nxt * KK + prv] + __ldg(fB + (size_t)t * FS + nxt);
    }
    #pragma unroll
    for (int o = 16; o; o >>= 1) {
        gA += __shfl_xor_sync(~0u, gA, o);
        gB += __shfl_xor_sync(~0u, gB, o);
    }

    int last = 0;
    if (lane == 0) {
        g_partial[bA] = logzA - (gA + s_trans[STOP_TAG * KK + __ldg(tgA + lenA - 1)]);
        g_partial[bB] = logzB - (gB + s_trans[STOP_TAG * KK + __ldg(tgB + lenB - 1)]);
        __threadfence();
        int prev = atomicAdd(&g_count, 1);
        last = (prev == NBLK - 1);
    }
    last = __shfl_sync(~0u, last, 0);

    if (last) {
        __threadfence();
        float a = 0.0f;
        #pragma unroll
        for (int i = 0; i < BB / 32; i++)
            a += g_partial[lane + i * 32];
        #pragma unroll
        for (int o = 16; o; o >>= 1) a += __shfl_xor_sync(~0u, a, o);
        if (lane == 0) {
            out[0] = a;
            g_count = 0;                            // replay-safe reset
        }
    }
}

extern "C" void kernel_launch(void* const* d_in, const int* in_sizes, int n_in,
                              void* d_out, int out_size) {
    const float* feats   = (const float*)d_in[0];
    const float* trans   = (const float*)d_in[1];
    const int*   tags    = (const int*)d_in[2];
    const int*   lengths = (const int*)d_in[3];
    crf_kernel<<<NBLK, 32>>>(feats, trans, tags, lengths, (float*)d_out);
}

// round 6
// speedup vs baseline: 1.3259x; 1.3259x over previous
#include <cuda_runtime.h>

// CRF loss, T=512, B=1024, K=48. One 32-thread warp per batch element (grid
// 1024 = single wave). Lanes 0..23 own output-state pair (2l, 2l+1).
// Linear-space recursion, exact power-of-2 renorm (int exponent accumulator).
// Natural float2 packing: smem P stored {P_2i, P_2i+1}; one broadcast LDS.128
// feeds 4 input states; 48 fma.rn.f32x2 across 8 accumulators (depth 6).
// exp(feat) computed 6 steps ahead in the prefetch shadow (MUFU off-path).

#define TT 512
#define BB 1024
#define KK 48
#define START_TAG 46
#define STOP_TAG  47
#define LN2F 0.6931471805599453f
#define PFD 6                      // prefetch depth

__device__ float g_partial[BB];
__device__ int   g_count = 0;      // last block resets to 0 (graph-replay safe)

__device__ __forceinline__ unsigned long long pack2(float lo, float hi) {
    unsigned long long r;
    asm("mov.b64 %0, {%1, %2};" : "=l"(r) : "f"(lo), "f"(hi));
    return r;
}
__device__ __forceinline__ void unpack2(unsigned long long v, float& lo, float& hi) {
    asm("mov.b64 {%0, %1}, %2;" : "=f"(lo), "=f"(hi) : "l"(v));
}
__device__ __forceinline__ unsigned long long fma2(unsigned long long a,
                                                   unsigned long long b,
                                                   unsigned long long c) {
    unsigned long long d;
    asm("fma.rn.f32x2 %0, %1, %2, %3;" : "=l"(d) : "l"(a), "l"(b), "l"(c));
    return d;
}
__device__ __forceinline__ unsigned long long add2(unsigned long long a,
                                                   unsigned long long b) {
    unsigned long long d;
    asm("add.rn.f32x2 %0, %1, %2;" : "=l"(d) : "l"(a), "l"(b));
    return d;
}

__global__ void __launch_bounds__(32, 1) crf_kernel(
    const float* __restrict__ feats,
    const float* __restrict__ trans,
    const int*   __restrict__ tags,
    const int*   __restrict__ lengths,
    float*       __restrict__ out)
{
    __shared__ __align__(16) float2 s_p[2][24];    // {P_2i, P_2i+1}, ping-pong
    __shared__ float s_trans[KK * KK];

    const int b    = blockIdx.x;
    const int lane = threadIdx.x;
    const bool act = (lane < 24);
    const int s0 = 2 * lane;
    const int s1 = 2 * lane + 1;
    const int len = __ldg(lengths + b);

    for (int i = lane; i < KK * KK; i += 32) s_trans[i] = trans[i];
    for (int i = lane; i < 24; i += 32) {
        float2 z = make_float2(0.0f, 0.0f);
        s_p[0][i] = (i == 23) ? make_float2(1.0f, 0.0f) : z;  // START=46
        s_p[1][i] = z;
    }
    __syncwarp();

    // etp0[i] = {exp(T[s0,2i]), exp(T[s0,2i+1])}, etp1 likewise for s1
    unsigned long long etp0[24], etp1[24];
    if (act) {
        #pragma unroll
        for (int i = 0; i < 24; i++) {
            etp0[i] = pack2(__expf(s_trans[s0 * KK + 2*i]),
                            __expf(s_trans[s0 * KK + 2*i + 1]));
            etp1[i] = pack2(__expf(s_trans[s1 * KK + 2*i]),
                            __expf(s_trans[s1 * KK + 2*i + 1]));  // exp(-1e4)=0
        }
    }

    const float* fb = feats + b * KK;
    const size_t FS = (size_t)BB * KK;              // floats per time step

    // raw-feat prefetch pipeline, depth 6; running pointer (no per-iter IMAD)
    float2 r1 = {0,0}, r2 = {0,0}, r3 = {0,0}, r4 = {0,0}, r5 = {0,0}, r6 = {0,0};
    if (act) {
        r1 = __ldg((const float2*)(fb + s0));
        if (1 < len) r2 = __ldg((const float2*)(fb + 1 * FS + s0));
        if (2 < len) r3 = __ldg((const float2*)(fb + 2 * FS + s0));
        if (3 < len) r4 = __ldg((const float2*)(fb + 3 * FS + s0));
        if (4 < len) r5 = __ldg((const float2*)(fb + 4 * FS + s0));
        if (5 < len) r6 = __ldg((const float2*)(fb + 5 * FS + s0));
    }
    const float2* pf = (const float2*)(fb + s0) + (size_t)PFD * (FS / 2);
    const int pre = len - PFD;                      // loads valid while t < pre

    int Cint = 0;
    __syncwarp();

    int buf = 0;
    #pragma unroll 1
    for (int t = 0; t < len; t++) {
        float2 fc = r1;
        r1 = r2; r2 = r3; r3 = r4; r4 = r5; r5 = r6;
        if (act) {
            r6 = (t < pre) ? __ldg(pf) : make_float2(0.0f, 0.0f);
            pf += FS / 2;
        }

        if (act) {
            // exp of a feat loaded 6 steps ago: MUFU runs under the chain
            float ef0 = __expf(fc.x);
            float ef1 = __expf(fc.y);

            const ulonglong2* pv = (const ulonglong2*)(s_p[buf]);
            ulonglong2 e0 = pv[0];                   // states 0..3 (broadcast)
            float p0 = __uint_as_float((unsigned)e0.x);

            unsigned long long c0 = fma2(e0.x, etp0[0], 0ull);
            unsigned long long c2 = fma2(e0.y, etp0[1], 0ull);
            unsigned long long c4 = fma2(e0.x, etp1[0], 0ull);
            unsigned long long c6 = fma2(e0.y, etp1[1], 0ull);
            unsigned long long c1 = 0ull, c3 = 0ull, c5 = 0ull, c7 = 0ull;
            #pragma unroll
            for (int q = 1; q < 12; q++) {
                ulonglong2 e = pv[q];                // states 4q..4q+3
                if (q & 1) {
                    c1 = fma2(e.x, etp0[2*q],     c1);
                    c3 = fma2(e.y, etp0[2*q + 1], c3);
                    c5 = fma2(e.x, etp1[2*q],     c5);
                    c7 = fma2(e.y, etp1[2*q + 1], c7);
                } else {
                    c0 = fma2(e.x, etp0[2*q],     c0);
                    c2 = fma2(e.y, etp0[2*q + 1], c2);
                    c4 = fma2(e.x, etp1[2*q],     c4);
                    c6 = fma2(e.y, etp1[2*q + 1], c6);
                }
            }
            unsigned long long sum0 = add2(add2(c0, c1), add2(c2, c3));
            unsigned long long sum1 = add2(add2(c4, c5), add2(c6, c7));

            // exact power-of-2 renorm from P[0]'s exponent (parallel to chain)
            unsigned int pexp = ((unsigned)e0.x) >> 23;
            int pe = (pexp - 1u < 254u) ? (int)pexp - 127 : 0;
            Cint += pe;
            float k = __uint_as_float((unsigned)(127 - pe) << 23);
            float m0 = ef0 * k, m1 = ef1 * k;
            (void)p0;

            float l0, h0, l1, h1;
            unpack2(sum0, l0, h0);
            unpack2(sum1, l1, h1);
            s_p[buf ^ 1][lane] = make_float2((l0 + h0) * m0, (l1 + h1) * m1);
        }
        __syncwarp();
        buf ^= 1;
    }

    // log_z = Cint*ln2 + log( sum_j P_j * exp(trans[STOP, j]) )
    float v = 0.0f;
    if (act) {
        float2 P = s_p[len & 1][lane];
        v = P.x * __expf(s_trans[STOP_TAG * KK + s0])
          + P.y * __expf(s_trans[STOP_TAG * KK + s1]);
    }
    #pragma unroll
    for (int o = 16; o; o >>= 1) v += __shfl_xor_sync(~0u, v, o);
    float logz = (float)Cint * LN2F + __logf(v);    // lane 0's Cint valid

    // gold score: strided over t, warp reduce
    const int* tg = tags + b * TT;
    float g = 0.0f;
    for (int t = lane; t < len; t += 32) {
        int nxt = __ldg(tg + t);
        int prv = (t == 0) ? START_TAG : __ldg(tg + t - 1);
        g += s_trans[nxt * KK + prv] + __ldg(fb + (size_t)t * FS + nxt);
    }
    #pragma unroll
    for (int o = 16; o; o >>= 1) g += __shfl_xor_sync(~0u, g, o);

    int last = 0;
    if (lane == 0) {
        float gold = g + s_trans[STOP_TAG * KK + __ldg(tg + len - 1)];
        g_partial[b] = logz - gold;
        __threadfence();
        int prev = atomicAdd(&g_count, 1);
        last = (prev == BB - 1);
    }
    last = __shfl_sync(~0u, last, 0);

    // last block: deterministic fixed-order final reduction, reset counter
    if (last) {
        __threadfence();
        float a = 0.0f;
        #pragma unroll
        for (int i = 0; i < BB / 32; i++)
            a += g_partial[lane + i * 32];
        #pragma unroll
        for (int o = 16; o; o >>= 1) a += __shfl_xor_sync(~0u, a, o);
        if (lane == 0) {
            out[0] = a;
            g_count = 0;                            // replay-safe reset
        }
    }
}

extern "C" void kernel_launch(void* const* d_in, const int* in_sizes, int n_in,
                              void* d_out, int out_size) {
    const float* feats   = (const float*)d_in[0];
    const float* trans   = (const float*)d_in[1];
    const int*   tags    = (const int*)d_in[2];
    const int*   lengths = (const int*)d_in[3];
    crf_kernel<<<BB, 32>>>(feats, trans, tags, lengths, (float*)d_out);
}